// round 1
// baseline (speedup 1.0000x reference)
#include <cuda_runtime.h>

// Problem constants (fixed by the dataset)
#define B_SZ   32768
#define IN_DIM 128
#define ACT    512
#define MAXD   1024

// Tiling
#define TM  64
#define TN  64
#define KC  64
#define LDA 132            // inputs tile leading dim (multiple of 4 for float4 stores)
#define LDB 65             // B tiles leading dim (odd -> conflict-free strided reads)

#define SA_FLOATS (TM * LDA)           // 8448
#define BT_FLOATS (TN * LDB)           // 4160
#define SMEM_FLOATS (SA_FLOATS + 4 * BT_FLOATS)   // 25088
#define SMEM_BYTES  (SMEM_FLOATS * 4)             // 100352

__device__ __forceinline__ float sigmoidf_(float x) { return 1.0f / (1.0f + expf(-x)); }

__global__ __launch_bounds__(256, 2)
void gser_fused(const float* __restrict__ inputs,
                const float* __restrict__ prev,
                const float* __restrict__ Wres,
                const float* __restrict__ Win,
                const float* __restrict__ Wgate,
                const float* __restrict__ leakp,
                const float* __restrict__ thrp,
                float* __restrict__ out)
{
    const int bx  = blockIdx.x;           // 0..7 compute tiles, 8..15 zero-fill
    const int m0  = blockIdx.y * TM;
    const int tid = threadIdx.x;

    if (bx >= 8) {
        // Zero out[:, 512 + (bx-8)*64 : +64)
        const int n0 = ACT + (bx - 8) * TN;
        const float4 z4 = make_float4(0.f, 0.f, 0.f, 0.f);
        for (int f4 = tid; f4 < TM * (TN / 4); f4 += 256) {
            int r = f4 >> 4;          // 16 float4 per 64-col row
            int c = f4 & 15;
            reinterpret_cast<float4*>(out + (size_t)(m0 + r) * MAXD + n0)[c] = z4;
        }
        return;
    }

    const int n0 = bx * TN;
    const int tx = tid & 15;
    const int ty = tid >> 4;

    extern __shared__ float smem[];
    float* sA  = smem;                    // inputs tile [64][LDA], full K=128
    float* sB0 = sA  + SA_FLOATS;         // W_in tile   [n][k]
    float* sB1 = sB0 + BT_FLOATS;         // W_gate(i)   [n][k]
    float* sB2 = sB1 + BT_FLOATS;         // W_gate(f)   [n][k]
    float* sB3 = sB2 + BT_FLOATS;         // W_gate(o)   [n][k]

    float z[4][4]  = {};
    float gi[4][4] = {};
    float gf[4][4] = {};
    float go[4][4] = {};

    // ---- Load inputs tile once: sA[m][k], k = 0..127 ----
    {
        const float4* gin = reinterpret_cast<const float4*>(inputs + (size_t)m0 * IN_DIM);
        for (int f4 = tid; f4 < TM * (IN_DIM / 4); f4 += 256) {
            int m = f4 >> 5;           // 32 float4 per row
            int c = f4 & 31;
            float4 v = gin[m * 32 + c];
            float* d = sA + m * LDA + c * 4;
            d[0] = v.x; d[1] = v.y; d[2] = v.z; d[3] = v.w;
        }
    }

    // ---- Phase 1: K=128 over inputs, 4 B matrices (W_in, W_gate i/f/o) ----
    for (int kc = 0; kc < IN_DIM; kc += KC) {
        __syncthreads();
        // Load B tiles [n][k] (row n is contiguous in k in gmem -> coalesced)
        for (int f4 = tid; f4 < TN * (KC / 4); f4 += 256) {
            int n  = f4 >> 4;          // 16 float4 per 64-k row
            int c4 = f4 & 15;
            const float4 vin = *reinterpret_cast<const float4*>(Win   + (size_t)(n0 + n) * IN_DIM + kc + 4 * c4);
            const float4 vi  = *reinterpret_cast<const float4*>(Wgate + (size_t)(n0 + n) * IN_DIM + kc + 4 * c4);
            const float4 vf  = *reinterpret_cast<const float4*>(Wgate + (size_t)(512 + n0 + n) * IN_DIM + kc + 4 * c4);
            const float4 vo  = *reinterpret_cast<const float4*>(Wgate + (size_t)(1024 + n0 + n) * IN_DIM + kc + 4 * c4);
            float* p0 = sB0 + n * LDB + 4 * c4;
            float* p1 = sB1 + n * LDB + 4 * c4;
            float* p2 = sB2 + n * LDB + 4 * c4;
            float* p3 = sB3 + n * LDB + 4 * c4;
            p0[0] = vin.x; p0[1] = vin.y; p0[2] = vin.z; p0[3] = vin.w;
            p1[0] = vi.x;  p1[1] = vi.y;  p1[2] = vi.z;  p1[3] = vi.w;
            p2[0] = vf.x;  p2[1] = vf.y;  p2[2] = vf.z;  p2[3] = vf.w;
            p3[0] = vo.x;  p3[1] = vo.y;  p3[2] = vo.z;  p3[3] = vo.w;
        }
        __syncthreads();

        #pragma unroll 4
        for (int kk = 0; kk < KC; ++kk) {
            float a[4];
            #pragma unroll
            for (int i = 0; i < 4; i++) a[i] = sA[(ty + 16 * i) * LDA + kc + kk];
            #pragma unroll
            for (int j = 0; j < 4; j++) {
                const int n = tx + 16 * j;
                const float b0 = sB0[n * LDB + kk];
                const float b1 = sB1[n * LDB + kk];
                const float b2 = sB2[n * LDB + kk];
                const float b3 = sB3[n * LDB + kk];
                #pragma unroll
                for (int i = 0; i < 4; i++) {
                    z[i][j]  += a[i] * b0;
                    gi[i][j] += a[i] * b1;
                    gf[i][j] += a[i] * b2;
                    go[i][j] += a[i] * b3;
                }
            }
        }
    }

    // ---- Phase 2: reservoir z += prev[m, :512] @ W_res[:512, n0:n0+64] ----
    float* sP = sB0;   // prev tile [m][k]
    float* sW = sB1;   // W_res tile [k][n]
    for (int kc = 0; kc < ACT; kc += KC) {
        __syncthreads();
        for (int f4 = tid; f4 < TM * (KC / 4); f4 += 256) {
            int r  = f4 >> 4;
            int c4 = f4 & 15;
            // prev rows m0+r, cols kc..kc+63  -> sP[r][k]
            float4 vp = *reinterpret_cast<const float4*>(prev + (size_t)(m0 + r) * MAXD + kc + 4 * c4);
            float* pp = sP + r * LDB + 4 * c4;
            pp[0] = vp.x; pp[1] = vp.y; pp[2] = vp.z; pp[3] = vp.w;
            // W_res rows kc+r, cols n0..n0+63 -> sW[k][n]
            float4 vw = *reinterpret_cast<const float4*>(Wres + (size_t)(kc + r) * MAXD + n0 + 4 * c4);
            float* pw = sW + r * LDB + 4 * c4;
            pw[0] = vw.x; pw[1] = vw.y; pw[2] = vw.z; pw[3] = vw.w;
        }
        __syncthreads();

        #pragma unroll 8
        for (int kk = 0; kk < KC; ++kk) {
            float a[4], b[4];
            #pragma unroll
            for (int i = 0; i < 4; i++) a[i] = sP[(ty + 16 * i) * LDB + kk];
            #pragma unroll
            for (int j = 0; j < 4; j++) b[j] = sW[kk * LDB + tx + 16 * j];
            #pragma unroll
            for (int j = 0; j < 4; j++)
                #pragma unroll
                for (int i = 0; i < 4; i++)
                    z[i][j] += a[i] * b[j];
        }
    }

    // ---- Epilogue ----
    #pragma unroll
    for (int j = 0; j < 4; j++) {
        const int n_g = n0 + tx + 16 * j;
        const float lk = sigmoidf_(leakp[n_g]);
        const float th = log1pf(expf(thrp[n_g]));
        #pragma unroll
        for (int i = 0; i < 4; i++) {
            const int m_g = m0 + ty + 16 * i;
            const float p   = prev[(size_t)m_g * MAXD + n_g];
            const float igv = sigmoidf_(gi[i][j]);
            const float fgv = sigmoidf_(gf[i][j]);
            const float ogv = sigmoidf_(go[i][j]);
            float s = (1.0f - lk) * (fgv * p) + lk * tanhf(igv * z[i][j]);
            s *= ogv;
            s = (s > th) ? (s - th) : s;
            out[(size_t)m_g * MAXD + n_g] = s;
        }
    }
}

extern "C" void kernel_launch(void* const* d_in, const int* in_sizes, int n_in,
                              void* d_out, int out_size)
{
    const float* inputs = (const float*)d_in[0];
    const float* prev   = (const float*)d_in[1];
    const float* Wres   = (const float*)d_in[2];
    const float* Win    = (const float*)d_in[3];
    const float* Wgate  = (const float*)d_in[4];
    const float* leakp  = (const float*)d_in[5];
    const float* thrp   = (const float*)d_in[6];
    float* out = (float*)d_out;

    cudaFuncSetAttribute(gser_fused, cudaFuncAttributeMaxDynamicSharedMemorySize, SMEM_BYTES);

    dim3 grid(16, B_SZ / TM);   // x: 8 compute + 8 zero-fill tiles, y: row blocks
    gser_fused<<<grid, 256, SMEM_BYTES>>>(inputs, prev, Wres, Win, Wgate, leakp, thrp, out);
}

// round 3
// speedup vs baseline: 1.9727x; 1.9727x over previous
#include <cuda_runtime.h>
#include <cstdint>

#define B_SZ   32768
#define IN_DIM 128
#define ACT    512
#define MAXD   1024

#define S2 68     // phase-2 tile stride (floats), k-extent 64, 16B-aligned, group-cycling
#define S1 36     // phase-1 tile stride (floats), k-extent 32

// smem float offsets (phase regions are a union; phases separated by syncs)
#define OF_P2_PHI 0
#define OF_P2_PLO 4352
#define OF_P2_WHI 8704
#define OF_P2_WLO 13056
#define OF_P1_AHI 0
#define OF_P1_ALO 2304
#define OF_P1_G   4608            // mat m: hi at +m*4608, lo at +m*4608+2304
#define OF_LK 23040
#define OF_TH 23104
#define SM_FLOATS 23168
#define SMEM_BYTES (SM_FLOATS * 4)

__device__ __forceinline__ uint32_t smem_u32(const void* p) {
    uint32_t a;
    asm("{ .reg .u64 t; cvta.to.shared.u64 t, %1; cvt.u32.u64 %0, t; }" : "=r"(a) : "l"(p));
    return a;
}
__device__ __forceinline__ void ldsm4(uint32_t r[4], uint32_t a) {
    asm volatile("ldmatrix.sync.aligned.m8n8.x4.shared.b16 {%0,%1,%2,%3}, [%4];"
        : "=r"(r[0]), "=r"(r[1]), "=r"(r[2]), "=r"(r[3]) : "r"(a));
}
__device__ __forceinline__ void mma8(float c[4], const uint32_t a[4], uint32_t b0, uint32_t b1) {
    asm volatile("mma.sync.aligned.m16n8k8.row.col.f32.tf32.tf32.f32 "
        "{%0,%1,%2,%3},{%4,%5,%6,%7},{%8,%9},{%0,%1,%2,%3};"
        : "+f"(c[0]), "+f"(c[1]), "+f"(c[2]), "+f"(c[3])
        : "r"(a[0]), "r"(a[1]), "r"(a[2]), "r"(a[3]), "r"(b0), "r"(b1));
}
__device__ __forceinline__ void split2(float x, float& hi, float& lo) {
    hi = __uint_as_float(__float_as_uint(x) & 0xFFFFE000u);   // exact tf32 truncation (matches HW RZ)
    lo = x - hi;
}
__device__ __forceinline__ float epi(float z, float gi_, float gf_, float go_,
                                     float p, float lk, float th) {
    float ig = 1.0f / (1.0f + expf(-gi_));
    float fg = 1.0f / (1.0f + expf(-gf_));
    float og = 1.0f / (1.0f + expf(-go_));
    float s = (1.0f - lk) * (fg * p) + lk * tanhf(ig * z);
    s *= og;
    return (s > th) ? (s - th) : s;
}

__global__ __launch_bounds__(256, 2)
void gser_mma(const float* __restrict__ inputs,
              const float* __restrict__ prev,
              const float* __restrict__ Wres,
              const float* __restrict__ Win,
              const float* __restrict__ Wgate,
              const float* __restrict__ leakp,
              const float* __restrict__ thrp,
              float* __restrict__ out)
{
    const int bx  = blockIdx.x;              // 0..7 column block
    const int m0  = blockIdx.y * 64;
    const int n0  = bx * 64;
    const int tid = threadIdx.x;
    const int wid = tid >> 5;
    const int lane = tid & 31;
    const int warp_m = wid & 3;              // 4 warp rows x 16
    const int warp_n = wid >> 2;             // 2 warp cols x 32

    extern __shared__ float sm[];
    const uint32_t sb = smem_u32(sm);

    // ---- zero-fill pad region: out[m0:m0+64, 512+bx*64 : +64) ----
    {
        const float4 z4 = make_float4(0.f, 0.f, 0.f, 0.f);
        #pragma unroll
        for (int it = 0; it < 4; ++it) {
            int idx = tid + 256 * it;        // 0..1023
            int r = idx >> 4, q = idx & 15;
            *reinterpret_cast<float4*>(out + (size_t)(m0 + r) * MAXD + ACT + bx * 64 + 4 * q) = z4;
        }
    }

    // ---- leak / threshold transforms (once) ----
    if (tid < 64) {
        sm[OF_LK + tid] = 1.0f / (1.0f + expf(-leakp[n0 + tid]));
        sm[OF_TH + tid] = log1pf(expf(thrp[n0 + tid]));
    }

    // accumulators: acc[mat][ntile][4]; mat0=z, 1=i, 2=f, 3=o
    float acc[4][4][4];
    #pragma unroll
    for (int a = 0; a < 4; ++a)
        #pragma unroll
        for (int b = 0; b < 4; ++b)
            #pragma unroll
            for (int cI = 0; cI < 4; ++cI) acc[a][b][cI] = 0.0f;

    // ---- ldmatrix lane address bases ----
    const uint32_t kb16 = (lane & 8) ? 16u : 0u;
    // A-frag lanes: row = (lane&15), +16B if lane>=16
    const uint32_t aRow2 = (uint32_t)((warp_m * 16 + (lane & 15)) * S2 * 4) + ((lane >> 4) << 4);
    const uint32_t p2aHi = sb + OF_P2_PHI * 4 + aRow2;
    const uint32_t p2aLo = sb + OF_P2_PLO * 4 + aRow2;
    // B-frag lanes: row = (lane&7) + 8*(lane>=16), k +16B if (lane&8)
    const int bRow0 = warp_n * 32 + (lane & 7) + ((lane >> 4) << 3);
    const uint32_t p2bHi0 = sb + OF_P2_WHI * 4 + (uint32_t)(bRow0 * S2 * 4) + kb16;
    const uint32_t p2bLo0 = sb + OF_P2_WLO * 4 + (uint32_t)(bRow0 * S2 * 4) + kb16;
    const uint32_t p2bStep = 16u * S2 * 4u;  // np -> np+1 (16 n rows)

    const uint32_t aRow1 = (uint32_t)((warp_m * 16 + (lane & 15)) * S1 * 4) + ((lane >> 4) << 4);
    const uint32_t p1aHi = sb + OF_P1_AHI * 4 + aRow1;
    const uint32_t p1aLo = sb + OF_P1_ALO * 4 + aRow1;
    const uint32_t p1gB  = sb + OF_P1_G * 4 + (uint32_t)(bRow0 * S1 * 4) + kb16;
    const uint32_t p1gStep = 16u * S1 * 4u;

    // ================= Phase A: z += prev[:, :512] @ Wres[:512, n0:n0+64] =================
    for (int c = 0; c < 8; ++c) {
        const int kc = c * 64;
        __syncthreads();
        // prev tile [64m x 64k] -> hi/lo
        #pragma unroll
        for (int it = 0; it < 4; ++it) {
            int idx = tid + 256 * it;
            int r = idx >> 4, q = idx & 15;
            float4 v = *reinterpret_cast<const float4*>(prev + (size_t)(m0 + r) * MAXD + kc + 4 * q);
            float4 h, l;
            split2(v.x, h.x, l.x); split2(v.y, h.y, l.y);
            split2(v.z, h.z, l.z); split2(v.w, h.w, l.w);
            *reinterpret_cast<float4*>(sm + OF_P2_PHI + r * S2 + 4 * q) = h;
            *reinterpret_cast<float4*>(sm + OF_P2_PLO + r * S2 + 4 * q) = l;
        }
        // Wres tile transpose [64k x 64n] -> [n][k] hi/lo
        {
            const int w = tid >> 5, l = tid & 31;
            #pragma unroll
            for (int i = 0; i < 8; ++i) {
                const int kk = w * 8 + i;
                const float* src = Wres + (size_t)(kc + kk) * MAXD + n0;
                #pragma unroll
                for (int h2 = 0; h2 < 2; ++h2) {
                    const int n = h2 * 32 + l;
                    float hi, lo;
                    split2(src[n], hi, lo);
                    sm[OF_P2_WHI + n * S2 + kk] = hi;
                    sm[OF_P2_WLO + n * S2 + kk] = lo;
                }
            }
        }
        __syncthreads();

        #pragma unroll
        for (int ks = 0; ks < 8; ++ks) {
            uint32_t ah[4], al[4];
            ldsm4(ah, p2aHi + ks * 32);
            ldsm4(al, p2aLo + ks * 32);
            #pragma unroll
            for (int np = 0; np < 2; ++np) {
                uint32_t bh[4], bl[4];
                ldsm4(bh, p2bHi0 + np * p2bStep + ks * 32);
                ldsm4(bl, p2bLo0 + np * p2bStep + ks * 32);
                mma8(acc[0][2 * np],     ah, bh[0], bh[1]);
                mma8(acc[0][2 * np],     ah, bl[0], bl[1]);
                mma8(acc[0][2 * np],     al, bh[0], bh[1]);
                mma8(acc[0][2 * np + 1], ah, bh[2], bh[3]);
                mma8(acc[0][2 * np + 1], ah, bl[2], bl[3]);
                mma8(acc[0][2 * np + 1], al, bh[2], bh[3]);
            }
        }
    }

    // ================= Phase B: K=128 inputs GEMM (z += in@Win^T; gates) =================
    const float* wmat[4] = {
        Win   + (size_t)n0 * IN_DIM,
        Wgate + (size_t)n0 * IN_DIM,
        Wgate + (size_t)(ACT + n0) * IN_DIM,
        Wgate + (size_t)(2 * ACT + n0) * IN_DIM
    };

    for (int c = 0; c < 4; ++c) {
        const int kc = 32 * c;
        __syncthreads();
        #pragma unroll
        for (int it = 0; it < 2; ++it) {
            int idx = tid + 256 * it;        // 0..511
            int r = idx >> 3, q = idx & 7;
            float4 v = *reinterpret_cast<const float4*>(inputs + (size_t)(m0 + r) * IN_DIM + kc + 4 * q);
            float4 h, l;
            split2(v.x, h.x, l.x); split2(v.y, h.y, l.y);
            split2(v.z, h.z, l.z); split2(v.w, h.w, l.w);
            *reinterpret_cast<float4*>(sm + OF_P1_AHI + r * S1 + 4 * q) = h;
            *reinterpret_cast<float4*>(sm + OF_P1_ALO + r * S1 + 4 * q) = l;
        }
        #pragma unroll
        for (int mt = 0; mt < 4; ++mt) {
            const float* W = wmat[mt];
            #pragma unroll
            for (int it = 0; it < 2; ++it) {
                int idx = tid + 256 * it;
                int r = idx >> 3, q = idx & 7;
                float4 v = *reinterpret_cast<const float4*>(W + (size_t)r * IN_DIM + kc + 4 * q);
                float4 h, l;
                split2(v.x, h.x, l.x); split2(v.y, h.y, l.y);
                split2(v.z, h.z, l.z); split2(v.w, h.w, l.w);
                *reinterpret_cast<float4*>(sm + OF_P1_G + mt * 4608 + r * S1 + 4 * q) = h;
                *reinterpret_cast<float4*>(sm + OF_P1_G + mt * 4608 + 2304 + r * S1 + 4 * q) = l;
            }
        }
        __syncthreads();

        #pragma unroll
        for (int ks = 0; ks < 4; ++ks) {
            uint32_t ah[4], al[4];
            ldsm4(ah, p1aHi + ks * 32);
            ldsm4(al, p1aLo + ks * 32);
            #pragma unroll
            for (int mt = 0; mt < 4; ++mt) {
                #pragma unroll
                for (int np = 0; np < 2; ++np) {
                    uint32_t bh[4], bl[4];
                    ldsm4(bh, p1gB + (uint32_t)mt * (4608u * 4u) + np * p1gStep + ks * 32);
                    ldsm4(bl, p1gB + (uint32_t)mt * (4608u * 4u) + 2304u * 4u + np * p1gStep + ks * 32);
                    mma8(acc[mt][2 * np],     ah, bh[0], bh[1]);
                    mma8(acc[mt][2 * np],     ah, bl[0], bl[1]);
                    mma8(acc[mt][2 * np],     al, bh[0], bh[1]);
                    mma8(acc[mt][2 * np + 1], ah, bh[2], bh[3]);
                    mma8(acc[mt][2 * np + 1], ah, bl[2], bl[3]);
                    mma8(acc[mt][2 * np + 1], al, bh[2], bh[3]);
                }
            }
        }
    }

    // ================= Epilogue =================
    const int tq = lane >> 2, tr = lane & 3;
    const int mg0 = m0 + warp_m * 16 + tq;
    const int mg1 = mg0 + 8;
    #pragma unroll
    for (int nt = 0; nt < 4; ++nt) {
        const int cc = warp_n * 32 + nt * 8 + 2 * tr;
        const int ng = n0 + cc;
        const float lk0 = sm[OF_LK + cc],     lk1 = sm[OF_LK + cc + 1];
        const float th0 = sm[OF_TH + cc],     th1 = sm[OF_TH + cc + 1];
        const float2 p0 = *reinterpret_cast<const float2*>(prev + (size_t)mg0 * MAXD + ng);
        const float2 p1 = *reinterpret_cast<const float2*>(prev + (size_t)mg1 * MAXD + ng);
        float2 o0, o1;
        o0.x = epi(acc[0][nt][0], acc[1][nt][0], acc[2][nt][0], acc[3][nt][0], p0.x, lk0, th0);
        o0.y = epi(acc[0][nt][1], acc[1][nt][1], acc[2][nt][1], acc[3][nt][1], p0.y, lk1, th1);
        o1.x = epi(acc[0][nt][2], acc[1][nt][2], acc[2][nt][2], acc[3][nt][2], p1.x, lk0, th0);
        o1.y = epi(acc[0][nt][3], acc[1][nt][3], acc[2][nt][3], acc[3][nt][3], p1.y, lk1, th1);
        *reinterpret_cast<float2*>(out + (size_t)mg0 * MAXD + ng) = o0;
        *reinterpret_cast<float2*>(out + (size_t)mg1 * MAXD + ng) = o1;
    }
}

extern "C" void kernel_launch(void* const* d_in, const int* in_sizes, int n_in,
                              void* d_out, int out_size)
{
    const float* inputs = (const float*)d_in[0];
    const float* prev   = (const float*)d_in[1];
    const float* Wres   = (const float*)d_in[2];
    const float* Win    = (const float*)d_in[3];
    const float* Wgate  = (const float*)d_in[4];
    const float* leakp  = (const float*)d_in[5];
    const float* thrp   = (const float*)d_in[6];
    float* out = (float*)d_out;

    cudaFuncSetAttribute(gser_mma, cudaFuncAttributeMaxDynamicSharedMemorySize, SMEM_BYTES);

    dim3 grid(8, B_SZ / 64);
    gser_mma<<<grid, 256, SMEM_BYTES>>>(inputs, prev, Wres, Win, Wgate, leakp, thrp, out);
}